// round 1
// baseline (speedup 1.0000x reference)
#include <cuda_runtime.h>
#include <math.h>

// Shapes (hardcoded per reference)
#define V  32
#define B  128
#define P  256
#define J  75
#define S2 25
#define F1 500   // fc1 out
#define F2 200   // fc2 out
#define KX 800   // V*S2

// Scratch (device globals: no allocation allowed)
__device__ float g_z [V*B*J];      // SLayer output
__device__ float g_W [V*8*3];      // fused stage_1 weights  W[v,g,c] = sum_f w2[v,g,f]*w1[v,f,c]
__device__ float g_u1[V*B*S2];     // stage_2 pre-BN
__device__ float g_xT[KX*B];       // concat activations, transposed [k][b]
__device__ float g_y1[F1*B];       // fc1 post-BN, transposed [f][b]

// ---------------------------------------------------------------------------
// Kernel 0: fuse the two 1x1 convs: W[v,g,c] = sum_f w2[v,g,f] * w1[v,f,c]
__global__ void k_prew(const float* __restrict__ w1, const float* __restrict__ w2) {
    int idx = threadIdx.x;                 // 768 threads: V*8*3
    if (idx >= V*8*3) return;
    int v = idx / 24, r = idx % 24, g = r / 3, c = r % 3;
    float acc = 0.f;
    #pragma unroll 8
    for (int f = 0; f < 32; ++f)
        acc = fmaf(w2[(v*8+g)*32 + f], w1[(v*32+f)*3 + c], acc);
    g_W[idx] = acc;
}

// ---------------------------------------------------------------------------
// Kernel 1: transform + SLayer. One block per (v,b). blockDim = 96.
// Deterministic compaction of masked points by warp 0 via ballot.
__global__ void k_slayer(const float* __restrict__ births, const float* __restrict__ lifetimes,
                         const int* __restrict__ mask, const float* __restrict__ centers,
                         const float* __restrict__ sharpness) {
    int vb = blockIdx.x;
    int v  = vb >> 7;               // B = 128
    __shared__ float sqx[P], sqy[P];
    __shared__ int scnt;
    int tid = threadIdx.x;

    if (tid < 32) {
        int cnt = 0;
        int base = vb * P;
        #pragma unroll
        for (int c = 0; c < P/32; ++c) {
            int p = c*32 + tid;
            int mv = mask[base + p];
            float bb = births[base + p], ll = lifetimes[base + p];
            float dd = bb + ll + 0.01f;
            const float inv = 0.70710678118654752440f;
            float x = (bb + dd) * inv;
            float y = (dd - bb) * inv;
            if (y <= 0.1f) y = logf(y * 10.0f) * 0.1f + 0.1f;
            unsigned bal = __ballot_sync(0xffffffffu, mv != 0);
            if (mv) {
                int pos = cnt + __popc(bal & ((1u << tid) - 1u));
                sqx[pos] = x; sqy[pos] = y;
            }
            cnt += __popc(bal);
        }
        if (tid == 0) scnt = cnt;
    }
    __syncthreads();
    int n = scnt;

    if (tid < J) {
        int cj = (v*J + tid) * 2;
        float cx = centers[cj], cy = centers[cj+1];
        float sx = sharpness[cj];   sx *= sx;
        float sy = sharpness[cj+1]; sy *= sy;
        float acc = 0.f;
        for (int p = 0; p < n; ++p) {
            float dx = sqx[p] - cx;
            float dy = sqy[p] - cy;
            float d2 = fmaf(sx*dx, dx, sy*dy*dy);
            acc += __expf(-d2);
        }
        g_z[vb*J + tid] = acc;
    }
}

// ---------------------------------------------------------------------------
// Kernel 2: neighbor stack + fused stage_1 (max over 8 channels) + l1 linear.
// One block per (v,b). blockDim = 128.
__global__ void k_stage1(const float* __restrict__ l1_w, const float* __restrict__ l1_b) {
    int vb = blockIdx.x;
    int v  = vb >> 7;
    int b  = vb & 127;
    __shared__ float zc[3][J];
    __shared__ float sW[24];
    __shared__ float hh[J];
    int tid = threadIdx.x;

    for (int i = tid; i < 3*J; i += blockDim.x) {
        int c = i / J, j = i % J;
        int vv = (v + c - 1 + V) & (V - 1);
        zc[c][j] = g_z[(vv*B + b)*J + j];
    }
    if (tid < 24) sW[tid] = g_W[v*24 + tid];
    __syncthreads();

    if (tid < J) {
        float z0 = zc[0][tid], z1 = zc[1][tid], z2 = zc[2][tid];
        float m = -INFINITY;
        #pragma unroll
        for (int g = 0; g < 8; ++g) {
            float s = fmaf(sW[g*3+2], z2, fmaf(sW[g*3+1], z1, sW[g*3]*z0));
            m = fmaxf(m, s);
        }
        hh[tid] = m;
    }
    __syncthreads();

    if (tid < S2) {
        float acc = l1_b[v*S2 + tid];
        const float* wrow = l1_w + (v*S2 + tid) * J;
        #pragma unroll 5
        for (int j = 0; j < J; ++j)
            acc = fmaf(hh[j], wrow[j], acc);
        g_u1[vb*S2 + tid] = acc;
    }
}

// ---------------------------------------------------------------------------
// Kernel 3: BN1 (over batch per (v,o)) + l2 linear + ReLU, write transposed x.
// One block per v. blockDim = 256.
__global__ void k_stage2(const float* __restrict__ bn1_g, const float* __restrict__ bn1_b,
                         const float* __restrict__ l2_w, const float* __restrict__ l2_b) {
    int v = blockIdx.x;
    __shared__ float su[B*S2];      // 3200
    __shared__ float sw[S2*S2];     // 625
    __shared__ float sb[S2];
    __shared__ float smean[S2], sscale[S2], sbeta[S2];
    int tid = threadIdx.x;

    for (int i = tid; i < B*S2; i += blockDim.x)  su[i] = g_u1[v*B*S2 + i];
    for (int i = tid; i < S2*S2; i += blockDim.x) sw[i] = l2_w[v*S2*S2 + i];
    if (tid < S2) sb[tid] = l2_b[v*S2 + tid];
    __syncthreads();

    if (tid < S2) {
        int o = tid;
        float s = 0.f;
        for (int bb = 0; bb < B; ++bb) s += su[bb*S2 + o];
        float mean = s * (1.f / B);
        float varr = 0.f;
        for (int bb = 0; bb < B; ++bb) {
            float d = su[bb*S2 + o] - mean;
            varr = fmaf(d, d, varr);
        }
        varr *= (1.f / B);
        smean[o]  = mean;
        sscale[o] = bn1_g[v*S2 + o] * rsqrtf(varr + 1e-5f);
        sbeta[o]  = bn1_b[v*S2 + o];
    }
    __syncthreads();

    for (int i = tid; i < B*S2; i += blockDim.x) {
        int o = i % S2;
        su[i] = (su[i] - smean[o]) * sscale[o] + sbeta[o];
    }
    __syncthreads();

    for (int i = tid; i < B*S2; i += blockDim.x) {
        int bb = i / S2, p = i % S2;
        float acc = sb[p];
        #pragma unroll
        for (int o = 0; o < S2; ++o)
            acc = fmaf(su[bb*S2 + o], sw[p*S2 + o], acc);
        acc = fmaxf(acc, 0.f);
        g_xT[(v*S2 + p)*B + bb] = acc;
    }
}

// ---------------------------------------------------------------------------
__device__ __forceinline__ float warpSum(float v) {
    #pragma unroll
    for (int o = 16; o > 0; o >>= 1) v += __shfl_down_sync(0xffffffffu, v, o);
    return v;
}
// blockDim must be 128 (4 warps). All threads must call.
__device__ __forceinline__ float blockSum128(float v, float* sred) {
    int lane = threadIdx.x & 31, w = threadIdx.x >> 5;
    v = warpSum(v);
    if (lane == 0) sred[w] = v;
    __syncthreads();
    float t = sred[0] + sred[1] + sred[2] + sred[3];
    __syncthreads();
    return t;
}

// ---------------------------------------------------------------------------
// Kernel 4: fc1 (800->500) + BN2 (over batch per feature). 5 features/block.
// grid = 100, blockDim = 128 (thread = batch index).
#define FPB 5
__global__ void k_fc1(const float* __restrict__ fc1_w, const float* __restrict__ fc1_b,
                      const float* __restrict__ bn2_g, const float* __restrict__ bn2_b) {
    __shared__ float sw[FPB*KX];   // 4000 floats
    __shared__ float sred[4];
    int f0 = blockIdx.x * FPB;
    int tid = threadIdx.x;

    for (int i = tid; i < FPB*KX; i += 128) {
        int ff = i / KX, k = i % KX;
        sw[i] = fc1_w[(f0+ff)*KX + k];
    }
    __syncthreads();

    float acc[FPB];
    #pragma unroll
    for (int ff = 0; ff < FPB; ++ff) acc[ff] = fc1_b[f0+ff];
    for (int k = 0; k < KX; ++k) {
        float xv = g_xT[k*B + tid];
        #pragma unroll
        for (int ff = 0; ff < FPB; ++ff)
            acc[ff] = fmaf(sw[ff*KX + k], xv, acc[ff]);
    }
    for (int ff = 0; ff < FPB; ++ff) {
        float mean = blockSum128(acc[ff], sred) * (1.f / B);
        float d = acc[ff] - mean;
        float varr = blockSum128(d*d, sred) * (1.f / B);
        float scale = bn2_g[f0+ff] * rsqrtf(varr + 1e-5f);
        g_y1[(f0+ff)*B + tid] = d*scale + bn2_b[f0+ff];
    }
}

// ---------------------------------------------------------------------------
// Kernel 5: fc2 (500->200). 4 outputs/block. grid = 50, blockDim = 128.
#define OPB 4
__global__ void k_fc2(const float* __restrict__ fc2_w, const float* __restrict__ fc2_b,
                      float* __restrict__ out) {
    __shared__ float sw[OPB*F1];   // 2000 floats
    int o0 = blockIdx.x * OPB;
    int tid = threadIdx.x;

    for (int i = tid; i < OPB*F1; i += 128) {
        int oo = i / F1, f = i % F1;
        sw[i] = fc2_w[(o0+oo)*F1 + f];
    }
    __syncthreads();

    float acc[OPB];
    #pragma unroll
    for (int oo = 0; oo < OPB; ++oo) acc[oo] = fc2_b[o0+oo];
    for (int f = 0; f < F1; ++f) {
        float yv = g_y1[f*B + tid];
        #pragma unroll
        for (int oo = 0; oo < OPB; ++oo)
            acc[oo] = fmaf(sw[oo*F1 + f], yv, acc[oo]);
    }
    #pragma unroll
    for (int oo = 0; oo < OPB; ++oo)
        out[tid*F2 + o0 + oo] = acc[oo];
}

// ---------------------------------------------------------------------------
extern "C" void kernel_launch(void* const* d_in, const int* in_sizes, int n_in,
                              void* d_out, int out_size) {
    const float* births    = (const float*)d_in[0];
    const float* lifetimes = (const float*)d_in[1];
    const int*   mask      = (const int*)  d_in[2];
    const float* centers   = (const float*)d_in[3];
    const float* sharpness = (const float*)d_in[4];
    const float* w1        = (const float*)d_in[5];
    const float* w2        = (const float*)d_in[6];
    const float* l1_w      = (const float*)d_in[7];
    const float* l1_b      = (const float*)d_in[8];
    const float* bn1_g     = (const float*)d_in[9];
    const float* bn1_b     = (const float*)d_in[10];
    const float* l2_w      = (const float*)d_in[11];
    const float* l2_b      = (const float*)d_in[12];
    const float* fc1_w     = (const float*)d_in[13];
    const float* fc1_b     = (const float*)d_in[14];
    const float* bn2_g     = (const float*)d_in[15];
    const float* bn2_b     = (const float*)d_in[16];
    const float* fc2_w     = (const float*)d_in[17];
    const float* fc2_b     = (const float*)d_in[18];
    float* out = (float*)d_out;

    k_prew  <<<1, 768>>>(w1, w2);
    k_slayer<<<V*B, 96>>>(births, lifetimes, mask, centers, sharpness);
    k_stage1<<<V*B, 128>>>(l1_w, l1_b);
    k_stage2<<<V, 256>>>(bn1_g, bn1_b, l2_w, l2_b);
    k_fc1   <<<F1/FPB, 128>>>(fc1_w, fc1_b, bn2_g, bn2_b);
    k_fc2   <<<F2/OPB, 128>>>(fc2_w, fc2_b, out);
}

// round 2
// speedup vs baseline: 2.1932x; 2.1932x over previous
#include <cuda_runtime.h>
#include <math.h>

// Shapes (hardcoded per reference)
#define V  32
#define B  128
#define P  256
#define J  75
#define S2 25
#define F1 500   // fc1 out
#define F2 200   // fc2 out
#define KX 800   // V*S2

// Scratch (device globals: no allocation allowed)
__device__ float g_z [V*B*J];      // SLayer output
__device__ float g_xT[KX*B];       // concat activations, transposed [k][b]
__device__ float g_y1[F1*B];       // fc1 post-BN, transposed [f][b]

__device__ __forceinline__ float warpSum(float v) {
    #pragma unroll
    for (int o = 16; o > 0; o >>= 1) v += __shfl_down_sync(0xffffffffu, v, o);
    return v;
}

// ---------------------------------------------------------------------------
// Kernel 1: transform + SLayer. One block per (v, b-pair). blockDim = 160.
// Warp-ballot compaction of masked points (deterministic).
__global__ void k_slayer(const float* __restrict__ births, const float* __restrict__ lifetimes,
                         const int* __restrict__ mask, const float* __restrict__ centers,
                         const float* __restrict__ sharpness) {
    int blk = blockIdx.x;           // V * B/2 = 2048
    int v   = blk >> 6;
    int b0  = (blk & 63) << 1;
    __shared__ float sqx[2][P], sqy[2][P];
    __shared__ int scnt[2];
    int tid = threadIdx.x;

    if (tid < 64) {
        int w = tid >> 5, lane = tid & 31;
        int base = (v*B + b0 + w) * P;
        int cnt = 0;
        #pragma unroll
        for (int c = 0; c < P/32; ++c) {
            int p = c*32 + lane;
            int mv = mask[base + p];
            float bb = births[base + p], ll = lifetimes[base + p];
            float dd = bb + ll + 0.01f;
            const float inv = 0.70710678118654752440f;
            float x = (bb + dd) * inv;
            float y = (dd - bb) * inv;
            if (y <= 0.1f) y = __logf(y * 10.0f) * 0.1f + 0.1f;
            unsigned bal = __ballot_sync(0xffffffffu, mv != 0);
            if (mv) {
                int pos = cnt + __popc(bal & ((1u << lane) - 1u));
                sqx[w][pos] = x; sqy[w][pos] = y;
            }
            cnt += __popc(bal);
        }
        if (lane == 0) scnt[w] = cnt;
    }
    __syncthreads();

    if (tid < 2*J) {
        int w = (tid >= J);
        int j = tid - w*J;
        int n = scnt[w];
        int cj = (v*J + j) * 2;
        float cx = centers[cj], cy = centers[cj+1];
        float sx = sharpness[cj];   sx *= sx;
        float sy = sharpness[cj+1]; sy *= sy;
        float acc = 0.f;
        for (int p = 0; p < n; ++p) {
            float dx = sqx[w][p] - cx;
            float dy = sqy[w][p] - cy;
            float d2 = fmaf(sx*dx, dx, sy*dy*dy);
            acc += __expf(-d2);
        }
        g_z[(v*B + b0 + w)*J + j] = acc;
    }
}

// ---------------------------------------------------------------------------
// Kernel 2: prew + neighbor stack + stage_1(max) + l1 + BN1 + l2 + ReLU.
// One block per v. blockDim = 512. Static smem ~42.6 KB.
__global__ void k_mid(const float* __restrict__ w1, const float* __restrict__ w2,
                      const float* __restrict__ l1_w, const float* __restrict__ l1_b,
                      const float* __restrict__ bn1_g, const float* __restrict__ bn1_b,
                      const float* __restrict__ l2_w, const float* __restrict__ l2_b) {
    int v = blockIdx.x;
    __shared__ float sW[24];
    __shared__ float hh[64*J];       // 19.2 KB (half-batch staging)
    __shared__ float su[B*S2];       // 12.8 KB
    __shared__ float sl1[S2*J];      // 7.5 KB
    __shared__ float sl2[S2*S2];     // 2.5 KB
    __shared__ float smean[S2], sscale[S2], sbeta[S2], sb1[S2], sb2[S2];
    int tid = threadIdx.x;

    if (tid < 24) {                  // fused stage_1 weights: W = w2 @ w1
        int g = tid/3, c = tid%3;
        float acc = 0.f;
        #pragma unroll 8
        for (int f = 0; f < 32; ++f)
            acc = fmaf(w2[(v*8+g)*32 + f], w1[(v*32+f)*3 + c], acc);
        sW[tid] = acc;
    }
    for (int i = tid; i < S2*J;  i += 512) sl1[i] = l1_w[v*S2*J  + i];
    for (int i = tid; i < S2*S2; i += 512) sl2[i] = l2_w[v*S2*S2 + i];
    if (tid < S2) { sb1[tid] = l1_b[v*S2+tid]; sb2[tid] = l2_b[v*S2+tid]; sbeta[tid] = bn1_b[v*S2+tid]; }
    __syncthreads();

    int vm = (v + V - 1) & (V - 1), vp = (v + 1) & (V - 1);
    for (int half = 0; half < 2; ++half) {
        int bb0 = half * 64;
        for (int i = tid; i < 64*J; i += 512) {
            int bl = i / J, j = i % J, b = bb0 + bl;
            float z0 = g_z[(vm*B + b)*J + j];
            float z1 = g_z[(v *B + b)*J + j];
            float z2 = g_z[(vp*B + b)*J + j];
            float m = -INFINITY;
            #pragma unroll
            for (int g = 0; g < 8; ++g) {
                float s = fmaf(sW[g*3+2], z2, fmaf(sW[g*3+1], z1, sW[g*3]*z0));
                m = fmaxf(m, s);
            }
            hh[i] = m;
        }
        __syncthreads();
        for (int i = tid; i < S2*64; i += 512) {
            int o = i / 64, bl = i % 64;
            float acc = sb1[o];
            const float* hr = &hh[bl*J];
            const float* wr = &sl1[o*J];
            #pragma unroll 5
            for (int j = 0; j < J; ++j) acc = fmaf(hr[j], wr[j], acc);
            su[(bb0 + bl)*S2 + o] = acc;
        }
        __syncthreads();
    }

    // BN1 stats: one warp per output channel (warp-parallel, deterministic)
    int warp = tid >> 5, lane = tid & 31;
    for (int o = warp; o < S2; o += 16) {
        float s = 0.f;
        #pragma unroll
        for (int b = lane; b < B; b += 32) s += su[b*S2 + o];
        s = warpSum(s);
        s = __shfl_sync(0xffffffffu, s, 0);
        float mean = s * (1.f / B);
        float vv = 0.f;
        #pragma unroll
        for (int b = lane; b < B; b += 32) { float d = su[b*S2 + o] - mean; vv = fmaf(d, d, vv); }
        vv = warpSum(vv);
        if (lane == 0) { smean[o] = mean; sscale[o] = bn1_g[v*S2+o] * rsqrtf(vv*(1.f/B) + 1e-5f); }
    }
    __syncthreads();

    for (int i = tid; i < B*S2; i += 512) {
        int o = i % S2;
        su[i] = (su[i] - smean[o]) * sscale[o] + sbeta[o];
    }
    __syncthreads();

    // l2 + ReLU, write transposed [k][b]
    for (int i = tid; i < S2*B; i += 512) {
        int p = i / B, b = i % B;
        float acc = sb2[p];
        const float* ur = &su[b*S2];
        const float* wr = &sl2[p*S2];
        #pragma unroll
        for (int o = 0; o < S2; ++o) acc = fmaf(ur[o], wr[o], acc);
        g_xT[(v*S2 + p)*B + b] = fmaxf(acc, 0.f);
    }
}

// ---------------------------------------------------------------------------
// Kernel 3: fc1 (800->500) + BN2. 5 features/block, split-K (2x400).
// grid = 100, blockDim = 256.
#define FPB 5
__global__ void k_fc1(const float* __restrict__ fc1_w, const float* __restrict__ fc1_b,
                      const float* __restrict__ bn2_g, const float* __restrict__ bn2_b) {
    __shared__ float sw[FPB*KX];     // 16 KB
    __shared__ float part[FPB*B];    // 2.5 KB
    __shared__ float smean[FPB], sscale[FPB];
    int f0 = blockIdx.x * FPB;
    int tid = threadIdx.x;
    int half = tid >> 7, bb = tid & 127;

    for (int i = tid; i < FPB*KX; i += 256) sw[i] = fc1_w[f0*KX + i];
    __syncthreads();

    float acc[FPB];
    #pragma unroll
    for (int ff = 0; ff < FPB; ++ff) acc[ff] = half ? 0.f : fc1_b[f0+ff];
    int k0 = half * (KX/2);
    for (int k = k0; k < k0 + KX/2; ++k) {
        float xv = g_xT[k*B + bb];
        #pragma unroll
        for (int ff = 0; ff < FPB; ++ff)
            acc[ff] = fmaf(sw[ff*KX + k], xv, acc[ff]);
    }
    if (half) {
        #pragma unroll
        for (int ff = 0; ff < FPB; ++ff) part[ff*B + bb] = acc[ff];
    }
    __syncthreads();
    if (!half) {
        #pragma unroll
        for (int ff = 0; ff < FPB; ++ff) part[ff*B + bb] += acc[ff];
    }
    __syncthreads();

    // BN2 stats: warp ff reduces feature ff over batch
    int warp = tid >> 5, lane = tid & 31;
    if (warp < FPB) {
        float s = 0.f;
        #pragma unroll
        for (int b = lane; b < B; b += 32) s += part[warp*B + b];
        s = warpSum(s);
        s = __shfl_sync(0xffffffffu, s, 0);
        float mean = s * (1.f / B);
        float vv = 0.f;
        #pragma unroll
        for (int b = lane; b < B; b += 32) { float d = part[warp*B + b] - mean; vv = fmaf(d, d, vv); }
        vv = warpSum(vv);
        if (lane == 0) { smean[warp] = mean; sscale[warp] = bn2_g[f0+warp] * rsqrtf(vv*(1.f/B) + 1e-5f); }
    }
    __syncthreads();

    if (!half) {
        #pragma unroll
        for (int ff = 0; ff < FPB; ++ff)
            g_y1[(f0+ff)*B + bb] = (part[ff*B + bb] - smean[ff]) * sscale[ff] + bn2_b[f0+ff];
    }
}

// ---------------------------------------------------------------------------
// Kernel 4: fc2 (500->200). 4 outputs/block, split-K (2x250).
// grid = 50, blockDim = 256.
#define OPB 4
__global__ void k_fc2(const float* __restrict__ fc2_w, const float* __restrict__ fc2_b,
                      float* __restrict__ out) {
    __shared__ float sw[OPB*F1];     // 8 KB
    __shared__ float part[OPB*B];    // 2 KB
    int o0 = blockIdx.x * OPB;
    int tid = threadIdx.x;
    int half = tid >> 7, bb = tid & 127;

    for (int i = tid; i < OPB*F1; i += 256) sw[i] = fc2_w[o0*F1 + i];
    __syncthreads();

    float acc[OPB];
    #pragma unroll
    for (int oo = 0; oo < OPB; ++oo) acc[oo] = half ? 0.f : fc2_b[o0+oo];
    int f0 = half * (F1/2);
    for (int f = f0; f < f0 + F1/2; ++f) {
        float yv = g_y1[f*B + bb];
        #pragma unroll
        for (int oo = 0; oo < OPB; ++oo)
            acc[oo] = fmaf(sw[oo*F1 + f], yv, acc[oo]);
    }
    if (half) {
        #pragma unroll
        for (int oo = 0; oo < OPB; ++oo) part[oo*B + bb] = acc[oo];
    }
    __syncthreads();
    if (!half) {
        #pragma unroll
        for (int oo = 0; oo < OPB; ++oo)
            out[bb*F2 + o0 + oo] = acc[oo] + part[oo*B + bb];
    }
}

// ---------------------------------------------------------------------------
extern "C" void kernel_launch(void* const* d_in, const int* in_sizes, int n_in,
                              void* d_out, int out_size) {
    const float* births    = (const float*)d_in[0];
    const float* lifetimes = (const float*)d_in[1];
    const int*   mask      = (const int*)  d_in[2];
    const float* centers   = (const float*)d_in[3];
    const float* sharpness = (const float*)d_in[4];
    const float* w1        = (const float*)d_in[5];
    const float* w2        = (const float*)d_in[6];
    const float* l1_w      = (const float*)d_in[7];
    const float* l1_b      = (const float*)d_in[8];
    const float* bn1_g     = (const float*)d_in[9];
    const float* bn1_b     = (const float*)d_in[10];
    const float* l2_w      = (const float*)d_in[11];
    const float* l2_b      = (const float*)d_in[12];
    const float* fc1_w     = (const float*)d_in[13];
    const float* fc1_b     = (const float*)d_in[14];
    const float* bn2_g     = (const float*)d_in[15];
    const float* bn2_b     = (const float*)d_in[16];
    const float* fc2_w     = (const float*)d_in[17];
    const float* fc2_b     = (const float*)d_in[18];
    float* out = (float*)d_out;

    k_slayer<<<V*B/2, 160>>>(births, lifetimes, mask, centers, sharpness);
    k_mid   <<<V, 512>>>(w1, w2, l1_w, l1_b, bn1_g, bn1_b, l2_w, l2_b);
    k_fc1   <<<F1/FPB, 256>>>(fc1_w, fc1_b, bn2_g, bn2_b);
    k_fc2   <<<F2/OPB, 256>>>(fc2_w, fc2_b, out);
}